// round 16
// baseline (speedup 1.0000x reference)
#include <cuda_runtime.h>
#include <cstdint>

#define NROWS 8192
#define HID   1024
#define PROJ  128
#define NSPLIT 4

// ---- scratch (device globals; no runtime allocation allowed) ----
__device__ __align__(16) float g_h[NROWS * HID];     // raw gelu(xW+b), fp32
__device__ __align__(16) float g_z[NROWS * PROJ];    // projection (fp32 exact)
__device__ __align__(16) float g_zt[NROWS * PROJ];   // z tf32-rounded
__device__ __align__(16) float g_wt[HID * HID];      // dense_w tf32-rounded
__device__ __align__(16) float g_dwt[HID * PROJ];    // dec_w tf32-rounded
__device__ float g_ps [16 * NROWS];                  // per-colblock partial sum(h)
__device__ float g_ps2[16 * NROWS];                  // per-colblock partial sum(h^2)
__device__ float g_mu[NROWS];
__device__ float g_iv[NROWS];
__device__ float g_m[NSPLIT * NROWS];
__device__ float g_s[NSPLIT * NROWS];
__device__ float g_pos[NROWS];

#define C2F  20.6099291555566200f   // log2(e)/T
#define LN2F 0.6931471805599453f
#define INVT 14.2857142857142857f

// ==================== helpers ====================
__device__ __forceinline__ uint32_t smem_u32(const void* p) {
    uint32_t a;
    asm("{ .reg .u64 t; cvta.to.shared.u64 t, %1; cvt.u32.u64 %0, t; }" : "=r"(a) : "l"(p));
    return a;
}
__device__ __forceinline__ float ex2(float x) {
    float y; asm("ex2.approx.f32 %0, %1;" : "=f"(y) : "f"(x)); return y;
}
__device__ __forceinline__ float tf32r(float x) {
    uint32_t o; asm("cvt.rna.tf32.f32 %0, %1;" : "=r"(o) : "f"(x));
    return __uint_as_float(o);
}
__device__ __forceinline__ uint32_t cvt32(float v) {
    uint32_t o; asm("cvt.rna.tf32.f32 %0, %1;" : "=r"(o) : "f"(v));
    return o;
}
__device__ __forceinline__ void mma8(float* d, const uint32_t* a, const uint32_t* b) {
    asm volatile("mma.sync.aligned.m16n8k8.row.col.f32.tf32.tf32.f32 "
        "{%0,%1,%2,%3}, {%4,%5,%6,%7}, {%8,%9}, {%0,%1,%2,%3};"
        : "+f"(d[0]), "+f"(d[1]), "+f"(d[2]), "+f"(d[3])
        : "r"(a[0]), "r"(a[1]), "r"(a[2]), "r"(a[3]), "r"(b[0]), "r"(b[1]));
}
__device__ __forceinline__ void cpa16(uint32_t s, const void* g) {
    asm volatile("cp.async.cg.shared.global [%0], [%1], 16;" :: "r"(s), "l"(g));
}
#define CP_COMMIT() asm volatile("cp.async.commit_group;" ::: "memory")
#define CP_WAIT0()  asm volatile("cp.async.wait_group 0;" ::: "memory")
#define CP_WAIT1()  asm volatile("cp.async.wait_group 1;" ::: "memory")

// =====================================================================
// k_rnd4: elementwise tf32 RNA rounding (float4)
// =====================================================================
__global__ __launch_bounds__(256) void k_rnd4(const float4* __restrict__ in,
                                              float4* __restrict__ out, int n4) {
    int i = blockIdx.x * 256 + threadIdx.x;
    if (i < n4) {
        float4 v = in[i];
        v.x = tf32r(v.x); v.y = tf32r(v.y); v.z = tf32r(v.z); v.w = tf32r(v.w);
        out[i] = v;
    }
}

// =====================================================================
// k_mm<TM, GELU, CVTA, ZOUT, STATS, AFFINE>: tiled tf32 GEMM.
// CVTA:  A raw fp32, round at fragment load.
// ZOUT:  epilogue also writes tf32r copy to g_zt (GEMM2 only).
// STATS: epilogue writes per-row partial sum/sumsq of C values to
//        g_ps/g_ps2[blockIdx.x*2+wn] (GEMM1 only; LN stats).
// AFFINE: A = ((h - mu[r]) * iv[r]) * gamma[k] + beta[k], rounded
//        (GEMM2 only; lng/lnb = gamma/beta).
// =====================================================================
template<int TM, bool GELU, bool CVTA, bool ZOUT, bool STATS, bool AFFINE>
__global__ __launch_bounds__(TM * 2, TM == 128 ? 2 : 4)
void k_mm(const float* __restrict__ A, const float* __restrict__ B,
          const float* __restrict__ bias, float* __restrict__ C,
          int K, int ldb, int N,
          const float* __restrict__ lng, const float* __restrict__ lnb) {
    extern __shared__ float sm[];
    const int THREADS = TM * 2;
    const int ASZ = TM * 36;       // [m][k] pad-4
    const int BSZ = 32 * 136;      // [k][n] pad-8
    const int tid = threadIdx.x, wid = tid >> 5, lane = tid & 31;
    const int wm = wid >> 1, wn = wid & 1;
    const int row0 = blockIdx.y * TM, col0 = blockIdx.x * 128;
    const uint32_t sb = smem_u32(sm);

    auto stage = [&](int kc, int buf) {
        const int kbase = kc * 32;
        for (int idx = tid; idx < TM * 8; idx += THREADS) {
            int m = idx >> 3, k4 = idx & 7;
            cpa16(sb + (uint32_t)(buf * ASZ + 36 * m + 4 * k4) * 4,
                  A + (size_t)(row0 + m) * K + kbase + 4 * k4);
        }
        for (int idx = tid; idx < 1024; idx += THREADS) {
            int k = idx >> 5, n4 = idx & 31;
            cpa16(sb + (uint32_t)(2 * ASZ + buf * BSZ + 136 * k + 4 * n4) * 4,
                  B + (size_t)(kbase + k) * ldb + col0 + 4 * n4);
        }
    };

    // AFFINE: preload mu/inv for this thread's 4 A-rows
    float muv[4], ivv[4];
    if (AFFINE) {
#pragma unroll
        for (int mf = 0; mf < 2; mf++)
#pragma unroll
            for (int j = 0; j < 2; j++) {
                const int r = row0 + wm * 32 + mf * 16 + j * 8 + (lane >> 2);
                muv[mf * 2 + j] = g_mu[r];
                ivv[mf * 2 + j] = g_iv[r];
            }
    }

    float acc[2][8][4];
#pragma unroll
    for (int mf = 0; mf < 2; mf++)
#pragma unroll
        for (int nf = 0; nf < 8; nf++)
#pragma unroll
            for (int e = 0; e < 4; e++) acc[mf][nf][e] = 0.f;

    const int NK = K / 32;
    stage(0, 0); CP_COMMIT();

#pragma unroll 1
    for (int kc = 0; kc < NK; kc++) {
        if (kc + 1 < NK) { stage(kc + 1, (kc + 1) & 1); CP_COMMIT(); CP_WAIT1(); }
        else CP_WAIT0();
        __syncthreads();
        const float* Ab = sm + (kc & 1) * ASZ;
        const float* Bb = sm + 2 * ASZ + (kc & 1) * BSZ;
#pragma unroll
        for (int ks = 0; ks < 4; ks++) {
            const int k0 = ks * 8 + (lane & 3);
            uint32_t a[2][4], b[8][2];
            float gg0, gg1, bb0, bb1;
            if (AFFINE) {
                const int kg = kc * 32 + k0;
                gg0 = __ldg(lng + kg);     gg1 = __ldg(lng + kg + 4);
                bb0 = __ldg(lnb + kg);     bb1 = __ldg(lnb + kg + 4);
            }
#pragma unroll
            for (int mf = 0; mf < 2; mf++) {
                const int m = wm * 32 + mf * 16 + (lane >> 2);
                if (AFFINE) {
                    const float m0 = muv[mf * 2], i0 = ivv[mf * 2];
                    const float m1 = muv[mf * 2 + 1], i1 = ivv[mf * 2 + 1];
                    a[mf][0] = cvt32(fmaf((Ab[36 * m + k0] - m0) * i0, gg0, bb0));
                    a[mf][1] = cvt32(fmaf((Ab[36 * (m + 8) + k0] - m1) * i1, gg0, bb0));
                    a[mf][2] = cvt32(fmaf((Ab[36 * m + k0 + 4] - m0) * i0, gg1, bb1));
                    a[mf][3] = cvt32(fmaf((Ab[36 * (m + 8) + k0 + 4] - m1) * i1, gg1, bb1));
                } else if (CVTA) {
                    a[mf][0] = cvt32(Ab[36 * m + k0]);
                    a[mf][1] = cvt32(Ab[36 * (m + 8) + k0]);
                    a[mf][2] = cvt32(Ab[36 * m + k0 + 4]);
                    a[mf][3] = cvt32(Ab[36 * (m + 8) + k0 + 4]);
                } else {
                    a[mf][0] = __float_as_uint(Ab[36 * m + k0]);
                    a[mf][1] = __float_as_uint(Ab[36 * (m + 8) + k0]);
                    a[mf][2] = __float_as_uint(Ab[36 * m + k0 + 4]);
                    a[mf][3] = __float_as_uint(Ab[36 * (m + 8) + k0 + 4]);
                }
            }
#pragma unroll
            for (int nf = 0; nf < 8; nf++) {
                const int n = wn * 64 + nf * 8 + (lane >> 2);
                b[nf][0] = __float_as_uint(Bb[136 * k0 + n]);
                b[nf][1] = __float_as_uint(Bb[136 * (k0 + 4) + n]);
            }
#pragma unroll
            for (int mf = 0; mf < 2; mf++)
#pragma unroll
                for (int nf = 0; nf < 8; nf++)
                    mma8(acc[mf][nf], a[mf], b[nf]);
        }
        __syncthreads();
    }

    // epilogue
    float bb[8][2];
#pragma unroll
    for (int nf = 0; nf < 8; nf++) {
        const int c = col0 + wn * 64 + nf * 8 + (lane & 3) * 2;
        bb[nf][0] = bias[c]; bb[nf][1] = bias[c + 1];
    }
#pragma unroll
    for (int mf = 0; mf < 2; mf++)
#pragma unroll
        for (int h = 0; h < 2; h++) {
            const int r = row0 + wm * 32 + mf * 16 + h * 8 + (lane >> 2);
            float s = 0.f, s2 = 0.f;
#pragma unroll
            for (int nf = 0; nf < 8; nf++) {
                const int c = col0 + wn * 64 + nf * 8 + (lane & 3) * 2;
                float v0 = acc[mf][nf][h * 2 + 0] + bb[nf][0];
                float v1 = acc[mf][nf][h * 2 + 1] + bb[nf][1];
                if (GELU) {
                    v0 = 0.5f * v0 * (1.0f + erff(v0 * 0.70710678118654752f));
                    v1 = 0.5f * v1 * (1.0f + erff(v1 * 0.70710678118654752f));
                }
                if (STATS) { s += v0 + v1; s2 += v0 * v0 + v1 * v1; }
                float2 o; o.x = v0; o.y = v1;
                *(float2*)&C[(size_t)r * N + c] = o;
                if (ZOUT) {
                    float2 t; t.x = tf32r(v0); t.y = tf32r(v1);
                    *(float2*)&g_zt[(size_t)r * PROJ + c] = t;
                }
            }
            if (STATS) {
#pragma unroll
                for (int d = 1; d <= 2; d <<= 1) {
                    s  += __shfl_xor_sync(0xffffffffu, s,  d);
                    s2 += __shfl_xor_sync(0xffffffffu, s2, d);
                }
                if ((lane & 3) == 0) {
                    const int slot = blockIdx.x * 2 + wn;
                    g_ps [slot * NROWS + r] = s;
                    g_ps2[slot * NROWS + r] = s2;
                }
            }
        }
}

// =====================================================================
// k_stats: per-row LN stats from the 16 per-colblock partials
// =====================================================================
__global__ __launch_bounds__(256) void k_stats() {
    const int r = blockIdx.x * 256 + threadIdx.x;
    float s = 0.f, s2 = 0.f;
#pragma unroll
    for (int p = 0; p < 16; p++) {
        s  += g_ps [p * NROWS + r];
        s2 += g_ps2[p * NROWS + r];
    }
    const float mu = s * (1.0f / HID);
    const float var = s2 * (1.0f / HID) - mu * mu;
    g_mu[r] = mu;
    g_iv[r] = rsqrtf(var + 1e-12f);
}

// =====================================================================
// k_pos: pos_i = z_i . z_{(i+N/2)%N}  (fp32 exact), one warp per row
// =====================================================================
__global__ __launch_bounds__(256) void k_pos() {
    const int gt   = blockIdx.x * 256 + threadIdx.x;
    const int row  = gt >> 5;
    const int lane = gt & 31;
    const int p    = (row + NROWS / 2) & (NROWS - 1);
    const float4 a = *(const float4*)&g_z[(size_t)row * PROJ + lane * 4];
    const float4 b = *(const float4*)&g_z[(size_t)p   * PROJ + lane * 4];
    float s = a.x*b.x + a.y*b.y + a.z*b.z + a.w*b.w;
#pragma unroll
    for (int m = 16; m; m >>= 1) s += __shfl_xor_sync(0xffffffffu, s, m);
    if (lane == 0) g_pos[row] = s;
}

// =====================================================================
// k_sims: fused z@z.T (tf32 mma.sync) + per-THREAD online logsumexp.
// Round-10 form: 256 threads, 8 warps (4x2), CTA = 128 rows x 2048
// cols (1 of 4 splits), 16 j-tiles of 128. A resident, B staged after
// compute. Slot-based per-thread lse; lanes merged once at the end.
// =====================================================================
#define SIMS_SMEM (2 * 128 * 132 * 4)

__global__ __launch_bounds__(256) void k_sims() {
    extern __shared__ float sm[];
    float* As = sm;                 // [m 128][k 132]
    float* Bs = sm + 128 * 132;     // [n 128][k 132]
    const int tid = threadIdx.x, wid = tid >> 5, lane = tid & 31;
    const int wm = wid >> 1, wn = wid & 1;
    const int i0 = blockIdx.x * 128;
    const int j0 = blockIdx.y * (NROWS / NSPLIT);
    const uint32_t sb = smem_u32(sm);

    // stage A (rows i0..i0+127 of g_zt)
    for (int idx = tid; idx < 4096; idx += 256) {
        int r = idx >> 5, k4 = idx & 31;
        cpa16(sb + (uint32_t)(132 * r + 4 * k4) * 4,
              g_zt + (size_t)(i0 + r) * PROJ + 4 * k4);
    }
    CP_COMMIT();

    auto stageB = [&](int jb) {
        for (int idx = tid; idx < 4096; idx += 256) {
            int r = idx >> 5, k4 = idx & 31;
            cpa16(sb + (uint32_t)(128 * 132 + 132 * r + 4 * k4) * 4,
                  g_zt + (size_t)(jb + r) * PROJ + 4 * k4);
        }
    };
    stageB(j0);
    CP_COMMIT();

    float rm[4], rs[4];
#pragma unroll
    for (int s = 0; s < 4; s++) { rm[s] = -1e30f; rs[s] = 0.f; }

#pragma unroll 1
    for (int jt = 0; jt < (NROWS / NSPLIT) / 128; jt++) {
        const int jb = j0 + jt * 128;
        CP_WAIT0();
        __syncthreads();

        float acc[2][8][4];
#pragma unroll
        for (int mf = 0; mf < 2; mf++)
#pragma unroll
            for (int nf = 0; nf < 8; nf++)
#pragma unroll
                for (int e = 0; e < 4; e++) acc[mf][nf][e] = 0.f;

#pragma unroll
        for (int ks = 0; ks < 16; ks++) {
            const int k0 = ks * 8 + (lane & 3);
            uint32_t a[2][4], b[8][2];
#pragma unroll
            for (int mf = 0; mf < 2; mf++) {
                const int m = wm * 32 + mf * 16 + (lane >> 2);
                a[mf][0] = __float_as_uint(As[132 * m + k0]);
                a[mf][1] = __float_as_uint(As[132 * (m + 8) + k0]);
                a[mf][2] = __float_as_uint(As[132 * m + k0 + 4]);
                a[mf][3] = __float_as_uint(As[132 * (m + 8) + k0 + 4]);
            }
#pragma unroll
            for (int nf = 0; nf < 8; nf++) {
                const int n = wn * 64 + nf * 8 + (lane >> 2);
                b[nf][0] = __float_as_uint(Bs[132 * n + k0]);
                b[nf][1] = __float_as_uint(Bs[132 * n + k0 + 4]);
            }
#pragma unroll
            for (int mf = 0; mf < 2; mf++)
#pragma unroll
                for (int nf = 0; nf < 8; nf++)
                    mma8(acc[mf][nf], a[mf], b[nf]);
        }
        __syncthreads();   // all warps done reading Bs
        if (jt + 1 < (NROWS / NSPLIT) / 128) { stageB(j0 + (jt + 1) * 128); CP_COMMIT(); }

        // per-thread slot-based online lse (no shuffles; overlaps cp.async)
#pragma unroll
        for (int mf = 0; mf < 2; mf++)
#pragma unroll
            for (int h = 0; h < 2; h++) {
                const int slot = mf * 2 + h;
                const int ig = i0 + wm * 32 + mf * 16 + h * 8 + (lane >> 2);
                float u[16];
                float tm = -1e30f;
#pragma unroll
                for (int nf = 0; nf < 8; nf++)
#pragma unroll
                    for (int e = 0; e < 2; e++) {
                        const int j = jb + wn * 64 + nf * 8 + (lane & 3) * 2 + e;
                        const float v = acc[mf][nf][h * 2 + e];
                        const float uu = (j == ig) ? -1e30f : v * C2F;
                        u[nf * 2 + e] = uu;
                        tm = fmaxf(tm, uu);
                    }
                const float nm = fmaxf(rm[slot], tm);
                float p = 0.f;
#pragma unroll
                for (int q = 0; q < 16; q++) p += ex2(u[q] - nm);
                rs[slot] = rs[slot] * ex2(rm[slot] - nm) + p;
                rm[slot] = nm;
            }
    }

    // merge: 4 lanes per row (lane&3), then the two wn halves via smem
    __syncthreads();
#pragma unroll
    for (int mf = 0; mf < 2; mf++)
#pragma unroll
        for (int h = 0; h < 2; h++) {
            const int slot = mf * 2 + h;
            float m = rm[slot], s = rs[slot];
#pragma unroll
            for (int d = 1; d <= 2; d <<= 1) {
                const float m2 = __shfl_xor_sync(0xffffffffu, m, d);
                const float s2 = __shfl_xor_sync(0xffffffffu, s, d);
                const float M = fmaxf(m, m2);
                s = s * ex2(m - M) + s2 * ex2(m2 - M);
                m = M;
            }
            rm[slot] = m; rs[slot] = s;
            const int r_l = wm * 32 + mf * 16 + h * 8 + (lane >> 2);
            if (wn == 0 && (lane & 3) == 0) { sm[r_l] = m; sm[128 + r_l] = s; }
        }
    __syncthreads();
    if (wn == 1 && (lane & 3) == 0) {
#pragma unroll
        for (int mf = 0; mf < 2; mf++)
#pragma unroll
            for (int h = 0; h < 2; h++) {
                const int slot = mf * 2 + h;
                const int r_l = wm * 32 + mf * 16 + h * 8 + (lane >> 2);
                const float m0 = sm[r_l], s0 = sm[128 + r_l];
                const float M = fmaxf(m0, rm[slot]);
                const float S = s0 * ex2(m0 - M) + rs[slot] * ex2(rm[slot] - M);
                g_m[blockIdx.y * NROWS + i0 + r_l] = M;
                g_s[blockIdx.y * NROWS + i0 + r_l] = S;
            }
    }
}

// =====================================================================
// k_final: merge splits, mean loss
// =====================================================================
__global__ __launch_bounds__(1024) void k_final(float* __restrict__ out) {
    const int tid = threadIdx.x;
    float local = 0.f;
    for (int r = tid; r < NROWS; r += 1024) {
        const float m0 = g_m[r];
        const float m1 = g_m[NROWS   + r];
        const float m2 = g_m[2*NROWS + r];
        const float m3 = g_m[3*NROWS + r];
        const float M  = fmaxf(fmaxf(m0, m1), fmaxf(m2, m3));
        const float S  = g_s[r]         * exp2f(m0 - M)
                       + g_s[NROWS+r]   * exp2f(m1 - M)
                       + g_s[2*NROWS+r] * exp2f(m2 - M)
                       + g_s[3*NROWS+r] * exp2f(m3 - M);
        const float lse = (M + log2f(S)) * LN2F;
        local += lse - g_pos[r] * INVT;
    }
    __shared__ float red[32];
#pragma unroll
    for (int m = 16; m; m >>= 1) local += __shfl_xor_sync(0xffffffffu, local, m);
    if ((tid & 31) == 0) red[tid >> 5] = local;
    __syncthreads();
    if (tid < 32) {
        float v = red[tid];
#pragma unroll
        for (int m = 16; m; m >>= 1) v += __shfl_xor_sync(0xffffffffu, v, m);
        if (tid == 0) out[0] = v * (1.0f / NROWS);
    }
}

// =====================================================================
extern "C" void kernel_launch(void* const* d_in, const int* in_sizes, int n_in,
                              void* d_out, int out_size) {
    const float* x       = (const float*)d_in[0];
    const float* dense_w = (const float*)d_in[1];
    const float* dense_b = (const float*)d_in[2];
    const float* ln_g    = (const float*)d_in[3];
    const float* ln_b    = (const float*)d_in[4];
    const float* dec_w   = (const float*)d_in[5];
    const float* dec_b   = (const float*)d_in[6];
    float* out = (float*)d_out;

    void *p_h, *p_wt, *p_dwt, *p_z;
    cudaGetSymbolAddress(&p_h,   g_h);
    cudaGetSymbolAddress(&p_wt,  g_wt);
    cudaGetSymbolAddress(&p_dwt, g_dwt);
    cudaGetSymbolAddress(&p_z,   g_z);

    // tf32-round the (small) weight operands only; x is rounded in-register
    k_rnd4<<<(HID*HID/4 + 255)/256, 256>>>((const float4*)dense_w, (float4*)p_wt, HID*HID/4);
    k_rnd4<<<(HID*PROJ/4 + 255)/256, 256>>>((const float4*)dec_w, (float4*)p_dwt, HID*PROJ/4);

    // GEMM1: h = gelu(x@W + b), raw fp32 out + per-colblock LN partials
    cudaFuncSetAttribute(k_mm<128, true, true, false, true, false>,
                         cudaFuncAttributeMaxDynamicSharedMemorySize, 71680);
    k_mm<128, true, true, false, true, false><<<dim3(HID/128, NROWS/128), 256, 71680>>>(
        x, (const float*)p_wt, dense_b, (float*)p_h, HID, HID, HID, nullptr, nullptr);

    k_stats<<<NROWS / 256, 256>>>();

    // GEMM2: z = LN(h) @ dec_w + dec_b; LN affine fused into A-fragment load
    cudaFuncSetAttribute(k_mm<64, false, false, true, false, true>,
                         cudaFuncAttributeMaxDynamicSharedMemorySize, 53248);
    k_mm<64, false, false, true, false, true><<<dim3(1, NROWS/64), 128, 53248>>>(
        (const float*)p_h, (const float*)p_dwt, dec_b, (float*)p_z, HID, PROJ, PROJ,
        ln_g, ln_b);

    k_pos<<<NROWS/8, 256>>>();

    cudaFuncSetAttribute(k_sims, cudaFuncAttributeMaxDynamicSharedMemorySize, SIMS_SMEM);
    k_sims<<<dim3(NROWS/128, NSPLIT), 256, SIMS_SMEM>>>();

    k_final<<<1, 1024>>>(out);
}

// round 17
// speedup vs baseline: 1.0864x; 1.0864x over previous
#include <cuda_runtime.h>
#include <cstdint>

#define NROWS 8192
#define HID   1024
#define PROJ  128
#define NTILE 64                 // 8192/128 row tiles
#define NPAIR 2080               // NTILE*(NTILE+1)/2
#define GRID_SIMS 148

// ---- scratch (device globals; no runtime allocation allowed) ----
__device__ __align__(16) float g_h[NROWS * HID];     // gelu(xW+b), then LN'd (tf32-rounded)
__device__ __align__(16) float g_z[NROWS * PROJ];    // projection (fp32 exact)
__device__ __align__(16) float g_zt[NROWS * PROJ];   // z tf32-rounded
__device__ __align__(16) float g_wt[HID * HID];      // dense_w tf32-rounded
__device__ __align__(16) float g_dwt[HID * PROJ];    // dec_w tf32-rounded
__device__ float g_rm[NPAIR * 128];                  // per-pair row-pass (max, sumexp2)
__device__ float g_rs[NPAIR * 128];
__device__ float g_cm[NPAIR * 128];                  // per-pair col-pass (targets tile J)
__device__ float g_cs[NPAIR * 128];
__device__ float g_pos[NROWS];
__device__ float g_loss[NROWS];

#define C2F  20.6099291555566200f   // log2(e)/T
#define LN2F 0.6931471805599453f
#define INVT 14.2857142857142857f

// ==================== helpers ====================
__device__ __forceinline__ uint32_t smem_u32(const void* p) {
    uint32_t a;
    asm("{ .reg .u64 t; cvta.to.shared.u64 t, %1; cvt.u32.u64 %0, t; }" : "=r"(a) : "l"(p));
    return a;
}
__device__ __forceinline__ float ex2(float x) {
    float y; asm("ex2.approx.f32 %0, %1;" : "=f"(y) : "f"(x)); return y;
}
__device__ __forceinline__ float tf32r(float x) {
    uint32_t o; asm("cvt.rna.tf32.f32 %0, %1;" : "=r"(o) : "f"(x));
    return __uint_as_float(o);
}
__device__ __forceinline__ uint32_t cvt32(float v) {
    uint32_t o; asm("cvt.rna.tf32.f32 %0, %1;" : "=r"(o) : "f"(v));
    return o;
}
__device__ __forceinline__ void mma8(float* d, const uint32_t* a, const uint32_t* b) {
    asm volatile("mma.sync.aligned.m16n8k8.row.col.f32.tf32.tf32.f32 "
        "{%0,%1,%2,%3}, {%4,%5,%6,%7}, {%8,%9}, {%0,%1,%2,%3};"
        : "+f"(d[0]), "+f"(d[1]), "+f"(d[2]), "+f"(d[3])
        : "r"(a[0]), "r"(a[1]), "r"(a[2]), "r"(a[3]), "r"(b[0]), "r"(b[1]));
}
__device__ __forceinline__ void cpa16(uint32_t s, const void* g) {
    asm volatile("cp.async.cg.shared.global [%0], [%1], 16;" :: "r"(s), "l"(g));
}
#define CP_COMMIT() asm volatile("cp.async.commit_group;" ::: "memory")
#define CP_WAIT0()  asm volatile("cp.async.wait_group 0;" ::: "memory")
#define CP_WAIT1()  asm volatile("cp.async.wait_group 1;" ::: "memory")

__device__ __forceinline__ void unrank(int t, int& I, int& J) {
    int i = 0;
    while (t >= NTILE - i) { t -= NTILE - i; i++; }
    I = i; J = i + t;
}

// =====================================================================
// k_rnd4: elementwise tf32 RNA rounding (float4)
// =====================================================================
__global__ __launch_bounds__(256) void k_rnd4(const float4* __restrict__ in,
                                              float4* __restrict__ out, int n4) {
    int i = blockIdx.x * 256 + threadIdx.x;
    if (i < n4) {
        float4 v = in[i];
        v.x = tf32r(v.x); v.y = tf32r(v.y); v.z = tf32r(v.z); v.w = tf32r(v.w);
        out[i] = v;
    }
}

// =====================================================================
// k_mm<TM, GELU, CVTA, ZOUT>: tiled tf32 GEMM (round-15 form).
// =====================================================================
template<int TM, bool GELU, bool CVTA, bool ZOUT>
__global__ __launch_bounds__(TM * 2, TM == 128 ? 2 : 4)
void k_mm(const float* __restrict__ A, const float* __restrict__ B,
          const float* __restrict__ bias, float* __restrict__ C,
          int K, int ldb, int N) {
    extern __shared__ float sm[];
    const int THREADS = TM * 2;
    const int ASZ = TM * 36;
    const int BSZ = 32 * 136;
    const int tid = threadIdx.x, wid = tid >> 5, lane = tid & 31;
    const int wm = wid >> 1, wn = wid & 1;
    const int row0 = blockIdx.y * TM, col0 = blockIdx.x * 128;
    const uint32_t sb = smem_u32(sm);

    auto stage = [&](int kc, int buf) {
        const int kbase = kc * 32;
        for (int idx = tid; idx < TM * 8; idx += THREADS) {
            int m = idx >> 3, k4 = idx & 7;
            cpa16(sb + (uint32_t)(buf * ASZ + 36 * m + 4 * k4) * 4,
                  A + (size_t)(row0 + m) * K + kbase + 4 * k4);
        }
        for (int idx = tid; idx < 1024; idx += THREADS) {
            int k = idx >> 5, n4 = idx & 31;
            cpa16(sb + (uint32_t)(2 * ASZ + buf * BSZ + 136 * k + 4 * n4) * 4,
                  B + (size_t)(kbase + k) * ldb + col0 + 4 * n4);
        }
    };

    float acc[2][8][4];
#pragma unroll
    for (int mf = 0; mf < 2; mf++)
#pragma unroll
        for (int nf = 0; nf < 8; nf++)
#pragma unroll
            for (int e = 0; e < 4; e++) acc[mf][nf][e] = 0.f;

    const int NK = K / 32;
    stage(0, 0); CP_COMMIT();

#pragma unroll 1
    for (int kc = 0; kc < NK; kc++) {
        if (kc + 1 < NK) { stage(kc + 1, (kc + 1) & 1); CP_COMMIT(); CP_WAIT1(); }
        else CP_WAIT0();
        __syncthreads();
        const float* Ab = sm + (kc & 1) * ASZ;
        const float* Bb = sm + 2 * ASZ + (kc & 1) * BSZ;
#pragma unroll
        for (int ks = 0; ks < 4; ks++) {
            const int k0 = ks * 8 + (lane & 3);
            uint32_t a[2][4], b[8][2];
#pragma unroll
            for (int mf = 0; mf < 2; mf++) {
                const int m = wm * 32 + mf * 16 + (lane >> 2);
                if (CVTA) {
                    a[mf][0] = cvt32(Ab[36 * m + k0]);
                    a[mf][1] = cvt32(Ab[36 * (m + 8) + k0]);
                    a[mf][2] = cvt32(Ab[36 * m + k0 + 4]);
                    a[mf][3] = cvt32(Ab[36 * (m + 8) + k0 + 4]);
                } else {
                    a[mf][0] = __float_as_uint(Ab[36 * m + k0]);
                    a[mf][1] = __float_as_uint(Ab[36 * (m + 8) + k0]);
                    a[mf][2] = __float_as_uint(Ab[36 * m + k0 + 4]);
                    a[mf][3] = __float_as_uint(Ab[36 * (m + 8) + k0 + 4]);
                }
            }
#pragma unroll
            for (int nf = 0; nf < 8; nf++) {
                const int n = wn * 64 + nf * 8 + (lane >> 2);
                b[nf][0] = __float_as_uint(Bb[136 * k0 + n]);
                b[nf][1] = __float_as_uint(Bb[136 * (k0 + 4) + n]);
            }
#pragma unroll
            for (int mf = 0; mf < 2; mf++)
#pragma unroll
                for (int nf = 0; nf < 8; nf++)
                    mma8(acc[mf][nf], a[mf], b[nf]);
        }
        __syncthreads();
    }

    float bb[8][2];
#pragma unroll
    for (int nf = 0; nf < 8; nf++) {
        const int c = col0 + wn * 64 + nf * 8 + (lane & 3) * 2;
        bb[nf][0] = bias[c]; bb[nf][1] = bias[c + 1];
    }
#pragma unroll
    for (int mf = 0; mf < 2; mf++)
#pragma unroll
        for (int h = 0; h < 2; h++) {
            const int r = row0 + wm * 32 + mf * 16 + h * 8 + (lane >> 2);
#pragma unroll
            for (int nf = 0; nf < 8; nf++) {
                const int c = col0 + wn * 64 + nf * 8 + (lane & 3) * 2;
                float v0 = acc[mf][nf][h * 2 + 0] + bb[nf][0];
                float v1 = acc[mf][nf][h * 2 + 1] + bb[nf][1];
                if (GELU) {
                    v0 = 0.5f * v0 * (1.0f + erff(v0 * 0.70710678118654752f));
                    v1 = 0.5f * v1 * (1.0f + erff(v1 * 0.70710678118654752f));
                }
                float2 o; o.x = v0; o.y = v1;
                *(float2*)&C[(size_t)r * N + c] = o;
                if (ZOUT) {
                    float2 t; t.x = tf32r(v0); t.y = tf32r(v1);
                    *(float2*)&g_zt[(size_t)r * PROJ + c] = t;
                }
            }
        }
}

// =====================================================================
// k_ln: warp-per-row LayerNorm in place (round-15 form)
// =====================================================================
__global__ __launch_bounds__(256) void k_ln(const float* __restrict__ gamma,
                                            const float* __restrict__ beta) {
    const int wid  = threadIdx.x >> 5;
    const int lane = threadIdx.x & 31;
    const int row  = blockIdx.x * 8 + wid;
    float4* hr = (float4*)(g_h + (size_t)row * HID);

    float4 v[8];
#pragma unroll
    for (int q = 0; q < 8; q++) v[q] = hr[lane + 32 * q];

    float s = 0.f;
#pragma unroll
    for (int q = 0; q < 8; q++) s += (v[q].x + v[q].y) + (v[q].z + v[q].w);
#pragma unroll
    for (int m = 16; m; m >>= 1) s += __shfl_xor_sync(0xffffffffu, s, m);
    const float mu = s * (1.0f / HID);

    float q2 = 0.f;
#pragma unroll
    for (int q = 0; q < 8; q++) {
        const float dx = v[q].x - mu, dy = v[q].y - mu;
        const float dz = v[q].z - mu, dw = v[q].w - mu;
        q2 += (dx * dx + dy * dy) + (dz * dz + dw * dw);
    }
#pragma unroll
    for (int m = 16; m; m >>= 1) q2 += __shfl_xor_sync(0xffffffffu, q2, m);
    const float inv = rsqrtf(q2 * (1.0f / HID) + 1e-12f);

    const float4* g4 = (const float4*)gamma;
    const float4* b4 = (const float4*)beta;
#pragma unroll
    for (int q = 0; q < 8; q++) {
        const float4 g  = g4[lane + 32 * q];
        const float4 be = b4[lane + 32 * q];
        float4 o;
        o.x = tf32r((v[q].x - mu) * inv * g.x + be.x);
        o.y = tf32r((v[q].y - mu) * inv * g.y + be.y);
        o.z = tf32r((v[q].z - mu) * inv * g.z + be.z);
        o.w = tf32r((v[q].w - mu) * inv * g.w + be.w);
        hr[lane + 32 * q] = o;
    }
}

// =====================================================================
// k_pos: pos_i = z_i . z_{(i+N/2)%N}  (fp32 exact), one warp per row
// =====================================================================
__global__ __launch_bounds__(256) void k_pos() {
    const int gt   = blockIdx.x * 256 + threadIdx.x;
    const int row  = gt >> 5;
    const int lane = gt & 31;
    const int p    = (row + NROWS / 2) & (NROWS - 1);
    const float4 a = *(const float4*)&g_z[(size_t)row * PROJ + lane * 4];
    const float4 b = *(const float4*)&g_z[(size_t)p   * PROJ + lane * 4];
    float s = a.x*b.x + a.y*b.y + a.z*b.z + a.w*b.w;
#pragma unroll
    for (int m = 16; m; m >>= 1) s += __shfl_xor_sync(0xffffffffu, s, m);
    if (lane == 0) g_pos[row] = s;
}

// =====================================================================
// k_sims: SYMMETRIC z@z.T. 148 CTAs, CTA g handles pairs t = g + 148p
// (upper triangle, 14-15 pairs each). Per pair (I,J): one 128x128 tf32
// MMA tile; row pass -> g_rm/g_rs[t] (rows of I over cols of J, diag
// masked when I==J); col pass (I!=J) -> g_cm/g_cs[t] (rows of J over
// cols of I, via per-column reduction). A/B triple-buffered, next
// pair's tiles prefetched under the epilogue.
// =====================================================================
#define TSZ (128 * 132)
#define SIMS_SMEM ((3 * TSZ + 1536) * 4)

__global__ __launch_bounds__(256) void k_sims() {
    extern __shared__ float sm[];
    const int tid = threadIdx.x, wid = tid >> 5, lane = tid & 31;
    const int wm = wid >> 1, wn = wid & 1;
    const int g = blockIdx.x;
    const int np = 14 + (g < (NPAIR - 14 * GRID_SIMS) ? 1 : 0);   // 8 CTAs get 15
    const uint32_t sb = smem_u32(sm);
    float* rowm = sm + 3 * TSZ;        // [2][128]
    float* rowp = rowm + 256;          // [2][128]
    float* colm = rowp + 256;          // [4][128]
    float* colp = colm + 512;          // [4][128]

    auto stageTile = [&](int rowTile, int buf) {
        const float* src = g_zt + (size_t)rowTile * 128 * PROJ;
        for (int idx = tid; idx < 4096; idx += 256) {
            int rr = idx >> 5, k4 = idx & 31;
            cpa16(sb + (uint32_t)(buf * TSZ + 132 * rr + 4 * k4) * 4,
                  src + (size_t)rr * PROJ + 4 * k4);
        }
    };

    { int I0, J0; unrank(g, I0, J0); stageTile(I0, 0); stageTile(J0, 2); }
    CP_COMMIT();

#pragma unroll 1
    for (int p = 0; p < np; p++) {
        const int t = g + GRID_SIMS * p;
        int I, J; unrank(t, I, J);
        CP_WAIT0();
        __syncthreads();
        const float* As = sm + (p % 3) * TSZ;
        const float* Bs = sm + ((p + 2) % 3) * TSZ;

        float acc[2][8][4];
#pragma unroll
        for (int mf = 0; mf < 2; mf++)
#pragma unroll
            for (int nf = 0; nf < 8; nf++)
#pragma unroll
                for (int e = 0; e < 4; e++) acc[mf][nf][e] = 0.f;

#pragma unroll
        for (int ks = 0; ks < 16; ks++) {
            const int k0 = ks * 8 + (lane & 3);
            uint32_t a[2][4], b[8][2];
#pragma unroll
            for (int mf = 0; mf < 2; mf++) {
                const int m = wm * 32 + mf * 16 + (lane >> 2);
                a[mf][0] = __float_as_uint(As[132 * m + k0]);
                a[mf][1] = __float_as_uint(As[132 * (m + 8) + k0]);
                a[mf][2] = __float_as_uint(As[132 * m + k0 + 4]);
                a[mf][3] = __float_as_uint(As[132 * (m + 8) + k0 + 4]);
            }
#pragma unroll
            for (int nf = 0; nf < 8; nf++) {
                const int n = wn * 64 + nf * 8 + (lane >> 2);
                b[nf][0] = __float_as_uint(Bs[132 * n + k0]);
                b[nf][1] = __float_as_uint(Bs[132 * n + k0 + 4]);
            }
#pragma unroll
            for (int mf = 0; mf < 2; mf++)
#pragma unroll
                for (int nf = 0; nf < 8; nf++)
                    mma8(acc[mf][nf], a[mf], b[nf]);
        }
        __syncthreads();   // tiles free for restage; smem scratch free

        if (p + 1 < np) {
            int I2, J2; unrank(g + GRID_SIMS * (p + 1), I2, J2);
            stageTile(I2, (p + 1) % 3);
            stageTile(J2, p % 3);
            CP_COMMIT();
        }

        const int ib = I << 7, jb = J << 7;

        // ---- row pass: rows of I over the 128 cols of J ----
#pragma unroll
        for (int mf = 0; mf < 2; mf++)
#pragma unroll
            for (int h = 0; h < 2; h++) {
                const int rl = wm * 32 + mf * 16 + h * 8 + (lane >> 2);
                const int ig = ib + rl;
                float u[16];
                float tm = -1e30f;
#pragma unroll
                for (int nf = 0; nf < 8; nf++)
#pragma unroll
                    for (int e = 0; e < 2; e++) {
                        const int j = jb + wn * 64 + nf * 8 + (lane & 3) * 2 + e;
                        const float uu = (j == ig) ? -1e30f
                                                   : acc[mf][nf][h * 2 + e] * C2F;
                        u[nf * 2 + e] = uu;
                        tm = fmaxf(tm, uu);
                    }
                float pp = 0.f;
#pragma unroll
                for (int q = 0; q < 16; q++) pp += ex2(u[q] - tm);
                // merge the 4 lanes (lane&3) sharing this row
#pragma unroll
                for (int d = 1; d <= 2; d <<= 1) {
                    const float m2 = __shfl_xor_sync(0xffffffffu, tm, d);
                    const float s2 = __shfl_xor_sync(0xffffffffu, pp, d);
                    const float nm = fmaxf(tm, m2);
                    pp = pp * ex2(tm - nm) + s2 * ex2(m2 - nm);
                    tm = nm;
                }
                if ((lane & 3) == 0) {
                    rowm[wn * 128 + rl] = tm;
                    rowp[wn * 128 + rl] = pp;
                }
            }
        __syncthreads();
        if (tid < 128) {
            const float m0 = rowm[tid], m1 = rowm[128 + tid];
            const float nm = fmaxf(m0, m1);
            const float S = rowp[tid] * ex2(m0 - nm) + rowp[128 + tid] * ex2(m1 - nm);
            g_rm[(size_t)t * 128 + tid] = nm;
            g_rs[(size_t)t * 128 + tid] = S;
        }

        // ---- col pass (I != J): rows of J over the 128 cols of I ----
        if (I != J) {
            float cm[16], cp[16];
#pragma unroll
            for (int nf = 0; nf < 8; nf++)
#pragma unroll
                for (int e = 0; e < 2; e++) {
                    const int idx = nf * 2 + e;
                    float m = fmaxf(fmaxf(acc[0][nf][e], acc[0][nf][2 + e]),
                                    fmaxf(acc[1][nf][e], acc[1][nf][2 + e]));
                    cm[idx] = m * C2F;
                }
            // global column max over the 8 lane-groups (lane>>2)
#pragma unroll
            for (int d = 4; d <= 16; d <<= 1)
#pragma unroll
                for (int idx = 0; idx < 16; idx++)
                    cm[idx] = fmaxf(cm[idx], __shfl_xor_sync(0xffffffffu, cm[idx], d));
#pragma unroll
            for (int nf = 0; nf < 8; nf++)
#pragma unroll
                for (int e = 0; e < 2; e++) {
                    const int idx = nf * 2 + e;
                    float s = ex2(acc[0][nf][e] * C2F - cm[idx])
                            + ex2(acc[0][nf][2 + e] * C2F - cm[idx])
                            + ex2(acc[1][nf][e] * C2F - cm[idx])
                            + ex2(acc[1][nf][2 + e] * C2F - cm[idx]);
                    cp[idx] = s;
                }
#pragma unroll
            for (int d = 4; d <= 16; d <<= 1)
#pragma unroll
                for (int idx = 0; idx < 16; idx++)
                    cp[idx] += __shfl_xor_sync(0xffffffffu, cp[idx], d);
            if ((lane >> 2) == 0) {
#pragma unroll
                for (int nf = 0; nf < 8; nf++)
#pragma unroll
                    for (int e = 0; e < 2; e++) {
                        const int idx = nf * 2 + e;
                        const int cl = wn * 64 + nf * 8 + (lane & 3) * 2 + e;
                        colm[wm * 128 + cl] = cm[idx];
                        colp[wm * 128 + cl] = cp[idx];
                    }
            }
            __syncthreads();
            if (tid < 128) {
                float M = colm[tid];
                M = fmaxf(M, colm[128 + tid]);
                M = fmaxf(M, colm[256 + tid]);
                M = fmaxf(M, colm[384 + tid]);
                float S = colp[tid]       * ex2(colm[tid]       - M)
                        + colp[128 + tid] * ex2(colm[128 + tid] - M)
                        + colp[256 + tid] * ex2(colm[256 + tid] - M)
                        + colp[384 + tid] * ex2(colm[384 + tid] - M);
                g_cm[(size_t)t * 128 + tid] = M;
                g_cs[(size_t)t * 128 + tid] = S;
            }
        }
    }
}

// =====================================================================
// k_loss: per-row merge of the 64 slots (64-I row-pairs + I col-pairs)
// =====================================================================
__global__ __launch_bounds__(256) void k_loss() {
    const int r  = blockIdx.x * 256 + threadIdx.x;
    const int I  = r >> 7;
    const int rl = r & 127;
    float M = -1e30f, S = 0.f;
    // row slots: pairs (I, J) for J = I..63; t = base(I) + (J - I)
    int t = I * NTILE - (I * (I - 1)) / 2;
    for (int J = I; J < NTILE; J++, t++) {
        const float m = g_rm[(size_t)t * 128 + rl];
        const float s = g_rs[(size_t)t * 128 + rl];
        const float nm = fmaxf(M, m);
        S = S * ex2(M - nm) + s * ex2(m - nm);
        M = nm;
    }
    // col slots: pairs (I2, I) for I2 = 0..I-1; t = base(I2) + (I - I2)
    int b = 0;
    for (int I2 = 0; I2 < I; I2++) {
        const int tt = b + (I - I2);
        const float m = g_cm[(size_t)tt * 128 + rl];
        const float s = g_cs[(size_t)tt * 128 + rl];
        const float nm = fmaxf(M, m);
        S = S * ex2(M - nm) + s * ex2(m - nm);
        M = nm;
        b += NTILE - I2;
    }
    const float lse = (M + log2f(S)) * LN2F;
    g_loss[r] = lse - g_pos[r] * INVT;
}

// =====================================================================
// k_sum: mean of g_loss
// =====================================================================
__global__ __launch_bounds__(1024) void k_sum(float* __restrict__ out) {
    const int tid = threadIdx.x;
    float local = 0.f;
    for (int r = tid; r < NROWS; r += 1024) local += g_loss[r];
    __shared__ float red[32];
#pragma unroll
    for (int m = 16; m; m >>= 1) local += __shfl_xor_sync(0xffffffffu, local, m);
    if ((tid & 31) == 0) red[tid >> 5] = local;
    __syncthreads();
    if (tid < 32) {
        float v = red[tid];
#pragma unroll
        for (int m = 16; m; m >>= 1) v += __shfl_xor_sync(0xffffffffu, v, m);
        if (tid == 0) out[0] = v * (1.0f / NROWS);
    }
}

// =====================================================================
extern "C" void kernel_launch(void* const* d_in, const int* in_sizes, int n_in,
                              void* d_out, int out_size) {
    const float* x       = (const float*)d_in[0];
    const float* dense_w = (const float*)d_in[1];
    const float* dense_b = (const float*)d_in[2];
    const float* ln_g    = (const float*)d_in[3];
    const float* ln_b    = (const float*)d_in[4];
    const float* dec_w   = (const float*)d_in[5];
    const float* dec_b   = (const float*)d_in[6];
    float* out = (float*)d_out;

    void *p_h, *p_wt, *p_dwt, *p_z;
    cudaGetSymbolAddress(&p_h,   g_h);
    cudaGetSymbolAddress(&p_wt,  g_wt);
    cudaGetSymbolAddress(&p_dwt, g_dwt);
    cudaGetSymbolAddress(&p_z,   g_z);

    // tf32-round the (small) weight operands only; x is rounded in-register
    k_rnd4<<<(HID*HID/4 + 255)/256, 256>>>((const float4*)dense_w, (float4*)p_wt, HID*HID/4);
    k_rnd4<<<(HID*PROJ/4 + 255)/256, 256>>>((const float4*)dec_w, (float4*)p_dwt, HID*PROJ/4);

    // GEMM1: h = gelu(x@W + b); A = raw x, rounded at fragment load
    cudaFuncSetAttribute(k_mm<128, true, true, false>,
                         cudaFuncAttributeMaxDynamicSharedMemorySize, 71680);
    k_mm<128, true, true, false><<<dim3(HID/128, NROWS/128), 256, 71680>>>(
        x, (const float*)p_wt, dense_b, (float*)p_h, HID, HID, HID);

    k_ln<<<NROWS / 8, 256>>>(ln_g, ln_b);

    // GEMM2: z = hn @ dec_w + dec_b; epilogue also emits g_zt = tf32r(z)
    cudaFuncSetAttribute(k_mm<64, false, false, true>,
                         cudaFuncAttributeMaxDynamicSharedMemorySize, 53248);
    k_mm<64, false, false, true><<<dim3(1, NROWS/64), 128, 53248>>>(
        (const float*)p_h, (const float*)p_dwt, dec_b, (float*)p_z, HID, PROJ, PROJ);

    k_pos<<<NROWS/8, 256>>>();

    cudaFuncSetAttribute(k_sims, cudaFuncAttributeMaxDynamicSharedMemorySize, SIMS_SMEM);
    k_sims<<<GRID_SIMS, 256, SIMS_SMEM>>>();

    k_loss<<<NROWS / 256, 256>>>();
    k_sum<<<1, 1024>>>(out);
}